// round 10
// baseline (speedup 1.0000x reference)
#include <cuda_runtime.h>
#include <cstdint>

#define DIM 85
#define B_ROWS 262144
#define TROWS 32
#define THREADS 256
#define NT (B_ROWS / TROWS)        // 8192 tiles
#define GRID 296                   // 2 persistent CTAs per SM
#define STAGES 4
#define TILE_F (TROWS * DIM)       // 2720 floats per array per tile
#define TILE_B (TILE_F * 4)        // 10880 bytes
#define STAGE_B (2 * TILE_B)       // 21760 bytes (in + tg)

#define OFF_MBAR 0                 // 4 mbarriers, 8 B each
#define OFF_SP   32
#define OFF_ST   (OFF_SP + THREADS * 4)
#define OFF_SU   (OFF_ST + THREADS * 4)
#define OFF_DATA (OFF_SU + THREADS * 4)              // 3104 (16B aligned)
#define SMEM_TOTAL (OFF_DATA + STAGES * STAGE_B)     // 90144 B -> 2 CTAs/SM

__device__ float g_partials[GRID];
__device__ int   g_count = 0;

__device__ __forceinline__ void mbar_init(uint32_t mbar, uint32_t cnt) {
    asm volatile("mbarrier.init.shared.b64 [%0], %1;" :: "r"(mbar), "r"(cnt) : "memory");
}
__device__ __forceinline__ void mbar_expect_tx(uint32_t mbar, uint32_t bytes) {
    asm volatile("mbarrier.arrive.expect_tx.shared.b64 _, [%0], %1;"
                 :: "r"(mbar), "r"(bytes) : "memory");
}
__device__ __forceinline__ void mbar_wait(uint32_t mbar, uint32_t parity) {
    asm volatile(
        "{\n\t"
        ".reg .pred P;\n\t"
        "W_%=:\n\t"
        "mbarrier.try_wait.parity.acquire.cta.shared::cta.b64 P, [%0], %1, 0x989680;\n\t"
        "@P bra D_%=;\n\t"
        "bra W_%=;\n\t"
        "D_%=:\n\t"
        "}" :: "r"(mbar), "r"(parity) : "memory");
}
__device__ __forceinline__ void bulk_g2s(uint32_t dst, const void* src,
                                         uint32_t bytes, uint32_t mbar) {
    asm volatile(
        "cp.async.bulk.shared::cta.global.mbarrier::complete_tx::bytes [%0], [%1], %2, [%3];"
        :: "r"(dst), "l"(src), "r"(bytes), "r"(mbar) : "memory");
}

__global__ __launch_bounds__(THREADS)
void qfd_tma4(const float* __restrict__ in, const float* __restrict__ tg,
              float* __restrict__ out)
{
    extern __shared__ __align__(16) unsigned char smraw[];
    float* sP = (float*)(smraw + OFF_SP);
    float* sT = (float*)(smraw + OFF_ST);
    float* sU = (float*)(smraw + OFF_SU);
    __shared__ float warp_part[THREADS / 32];
    __shared__ bool  s_is_last;

    const int tid = threadIdx.x;
    const int row = tid & (TROWS - 1);                 // 0..31
    const int seg = tid >> 5;                          // 0..7 (warp id)
    // segment table: lengths 11,11,11,11,11,10,10,10 ; kbeg 0,11,22,33,44,55,65,75
    const int len  = (seg < 5) ? 11 : 10;
    const int kbeg = 11 * seg - ((seg > 5) ? (seg - 5) : 0);
    const float fkend = (float)(kbeg + len);

    const uint32_t mb0 = (uint32_t)__cvta_generic_to_shared(smraw + OFF_MBAR);
    const uint32_t data_s = (uint32_t)__cvta_generic_to_shared(smraw + OFF_DATA);

    if (tid == 0) {
#pragma unroll
        for (int s = 0; s < STAGES; s++)
            mbar_init(mb0 + 8u * s, 1);
        asm volatile("fence.proxy.async.shared::cta;" ::: "memory");
    }
    __syncthreads();

    // ---- prologue: fill all 4 stages with tiles t0 + s*GRID ----
    const int t0 = blockIdx.x;
    if (tid == 0) {
#pragma unroll
        for (int s = 0; s < STAGES; s++) {
            int t = t0 + s * GRID;
            if (t < NT) {
                uint32_t mb = mb0 + 8u * s;
                uint32_t ds = data_s + (uint32_t)(s * STAGE_B);
                mbar_expect_tx(mb, STAGE_B);
                bulk_g2s(ds,          in + (size_t)t * TILE_F, TILE_B, mb);
                bulk_g2s(ds + TILE_B, tg + (size_t)t * TILE_F, TILE_B, mb);
            }
        }
    }

    float acc = 0.0f;

    int it = 0;
    for (int t = t0; t < NT; t += GRID, it++) {
        const int p  = it & (STAGES - 1);
        const int ph = (it >> 2) & 1;
        mbar_wait(mb0 + 8u * p, (uint32_t)ph);

        const float* in_sm = (const float*)(smraw + OFF_DATA + p * STAGE_B);
        const float* tg_sm = (const float*)(smraw + OFF_DATA + p * STAGE_B + TILE_B);
        const float* ri = in_sm + row * DIM + kbeg;
        const float* rt = tg_sm + row * DIM + kbeg;

        // 4-op recurrence:  U += d*R ; C += d ; R += C   (R = sum (k-i)*d_i)
        float C = 0.0f, R = 0.0f, U = 0.0f;
#pragma unroll
        for (int k = 0; k < 11; k++) {
            if (k < len) {
                float d = fabsf(ri[k] - rt[k]);
                U = fmaf(d, R, U);
                C += d;
                R += C;
            }
        }
        // per-segment absolute-index moment: T_abs = kend*P - R
        sP[tid] = C;
        sT[tid] = fmaf(fkend, C, -R);
        sU[tid] = U;
        __syncthreads();                          // stage p fully consumed

        // refill stage p with tile t + 4*GRID (decoupled TMA stream)
        int tn = t + STAGES * GRID;
        if (tid == 0 && tn < NT) {
            uint32_t mb = mb0 + 8u * p;
            uint32_t ds = data_s + (uint32_t)(p * STAGE_B);
            mbar_expect_tx(mb, STAGE_B);
            bulk_g2s(ds,          in + (size_t)tn * TILE_F, TILE_B, mb);
            bulk_g2s(ds + TILE_B, tg + (size_t)tn * TILE_F, TILE_B, mb);
        }

        // per-row combine of 8 segment partials (threads 0..31, one warp)
        if (tid < TROWS) {
            float Ps[8], Ts[8];
            float Ut = 0.0f, S = 0.0f;
#pragma unroll
            for (int s = 0; s < 8; s++) {
                Ps[s] = sP[s * TROWS + tid];
                Ts[s] = sT[s * TROWS + tid];
                Ut   += sU[s * TROWS + tid];
                S    += Ps[s];
            }
#pragma unroll
            for (int a = 0; a < 8; a++)
#pragma unroll
                for (int b = a + 1; b < 8; b++)
                    Ut = fmaf(Ps[a], Ts[b], fmaf(-Ts[a], Ps[b], Ut));
            acc += fmaf(S, S, -(2.0f / (float)DIM) * Ut);
        }
        __syncthreads();                          // protect sP/sT/sU reuse
    }

    // ---- block reduce per-thread accumulators (deterministic) ----
    for (int o = 16; o; o >>= 1)
        acc += __shfl_down_sync(0xffffffffu, acc, o);
    if ((tid & 31) == 0)
        warp_part[tid >> 5] = acc;
    __syncthreads();

    if (tid == 0) {
        float s = 0.0f;
#pragma unroll
        for (int i = 0; i < THREADS / 32; i++)
            s += warp_part[i];
        g_partials[blockIdx.x] = s;
        __threadfence();
        int old = atomicAdd(&g_count, 1);
        s_is_last = (old == GRID - 1);
    }
    __syncthreads();

    // ---- last-arriving block: final deterministic reduce in double ----
    if (s_is_last) {
        __shared__ double sd[THREADS];
        double a = 0.0;
#pragma unroll
        for (int j = 0; j < (GRID + THREADS - 1) / THREADS; j++) {
            int i = tid + j * THREADS;
            if (i < GRID) a += (double)g_partials[i];
        }
        sd[tid] = a;
        __syncthreads();
        for (int o = THREADS / 2; o; o >>= 1) {
            if (tid < o) sd[tid] += sd[tid + o];
            __syncthreads();
        }
        if (tid == 0) {
            out[0] = (float)(0.1 * sd[0]);
            g_count = 0;                          // self-reset for next replay
        }
    }
}

extern "C" void kernel_launch(void* const* d_in, const int* in_sizes, int n_in,
                              void* d_out, int out_size)
{
    const float* in = (const float*)d_in[0];
    const float* tg = (const float*)d_in[1];
    float* out = (float*)d_out;

    cudaFuncSetAttribute(qfd_tma4,
                         cudaFuncAttributeMaxDynamicSharedMemorySize, SMEM_TOTAL);
    qfd_tma4<<<GRID, THREADS, SMEM_TOTAL>>>(in, tg, out);
}